// round 16
// baseline (speedup 1.0000x reference)
#include <cuda_runtime.h>
#include <cuda_bf16.h>

typedef unsigned long long ull;

#define BB 8
#define TT 20
#define MM 512
#define FF 16
#define HH 128
#define G3 384
#define BM 4096
#define HALF 64
#define KK 10

// ---------------- scratch ----------------
__device__ __align__(128) float g_hid[BM * HH];
__device__ __align__(128) float g_p1[BM * HALF];
__device__ __align__(128) float g_p2[BM * HALF];
__device__ __align__(128) float g_e1[BM * HALF];
__device__ __align__(128) float g_e2[BM * HALF];
__device__ __align__(128) float g_amx[BB * MM * MM];
__device__ __align__(128) float g_cs[BB * 8 * MM];
__device__ __align__(128) float g_rnrm[BM];
__device__ __align__(128) float g_A[BB * MM * MM];
__device__ __align__(128) float g_Z[BM * HH];
__device__ __align__(128) float g_h1[BM * HH];
__device__ __align__(128) float g_Z2[BM * KK];
__device__ __align__(128) float g_sp[BM * KK];
__device__ __align__(128) float g_y[BM];
__device__ __align__(128) float g_wih4[FF * G3];
__device__ __align__(128) float g_whh4[HH * G3];   // pre-permuted Whh
__device__ __align__(128) float g_w1t[HH * HALF];  // W1 transposed [h][kk]
__device__ __align__(128) float g_w2t[HH * HALF];  // W2 transposed [h][kk]
__device__ float g_sumV;

// ---------------- helpers ----------------
__device__ __forceinline__ float ftanh_a(float x) {
    float r; asm("tanh.approx.f32 %0, %1;" : "=f"(r) : "f"(x)); return r;
}
__device__ __forceinline__ float fsig_a(float x) {
    return fmaf(ftanh_a(0.5f * x), 0.5f, 0.5f);
}
__device__ __forceinline__ ull fdup(float x) {
    ull r; asm("mov.b64 %0, {%1, %1};" : "=l"(r) : "f"(x)); return r;
}
__device__ __forceinline__ float2 fup(ull v) {
    float2 r; asm("mov.b64 {%0, %1}, %2;" : "=f"(r.x), "=f"(r.y) : "l"(v)); return r;
}
__device__ __forceinline__ void fma2(ull& d, ull a, ull b) {
    asm("fma.rn.f32x2 %0, %1, %2, %0;" : "+l"(d) : "l"(a), "l"(b));
}
__device__ __forceinline__ ull add2(ull a, ull b) {
    ull r; asm("add.rn.f32x2 %0, %1, %2;" : "=l"(r) : "l"(a), "l"(b)); return r;
}
__device__ __forceinline__ ull mul2(ull a, ull b) {
    ull r; asm("mul.rn.f32x2 %0, %1, %2;" : "=l"(r) : "l"(a), "l"(b)); return r;
}

// ============================================================================
// Kernel 0: permute Wih, Whh; transpose W1, W2; sumV.
// total elems = 6144 + 49152 + 8192 + 8192 = 71680 -> 280 blocks
// ============================================================================
__global__ void wperm_kernel(const float* __restrict__ Wih,
                             const float* __restrict__ Whh,
                             const float* __restrict__ W1,
                             const float* __restrict__ W2,
                             const float* __restrict__ V)
{
    int i = blockIdx.x * 256 + threadIdx.x;
    if (i < G3 * FF) {
        int f = i / G3, rem = i % G3;
        int wq = rem >> 7, r2 = rem & 127;
        int lane = r2 >> 2, e = r2 & 3;
        int g = wq * 128 + ((e >> 1) * 64) + 2 * lane + (e & 1);
        g_wih4[i] = Wih[g * FF + f];
    }
    int j = i - G3 * FF;
    if (j >= 0 && j < G3 * HH) {
        int k = j / G3, rem = j % G3;
        int wq = rem >> 7, r2 = rem & 127;
        int lane = r2 >> 2, e = r2 & 3;
        int g = wq * 128 + ((e >> 1) * 64) + 2 * lane + (e & 1);
        g_whh4[j] = Whh[g * HH + k];
    }
    int j2 = j - G3 * HH;
    if (j2 >= 0 && j2 < HH * HALF) {
        int h = j2 >> 6, kk = j2 & 63;
        g_w1t[j2] = W1[kk * HH + h];
    }
    int j3 = j2 - HH * HALF;
    if (j3 >= 0 && j3 < HH * HALF) {
        int h = j3 >> 6, kk = j3 & 63;
        g_w2t[j3] = W2[kk * HH + h];
    }
    if (i == 0) {
        float s = 0.f;
#pragma unroll
        for (int k = 0; k < HALF; k++) s += V[k];
        g_sumV = s;
    }
}

// ============================================================================
// Kernel 1: combined GRU (blocks 0..127) + conv/zk (blocks 128..143).
// ============================================================================
#define HS 36
#define NXT 16
__global__ void __launch_bounds__(256, 1) gru_conv_kernel(
    const float* __restrict__ X,
    const float* __restrict__ bih, const float* __restrict__ bhh,
    const float* __restrict__ b1,
    const float* __restrict__ cw, const float* __restrict__ cb,
    const float* __restrict__ clw, const float* __restrict__ clb,
    const float* __restrict__ gc1_W)
{
    extern __shared__ float sm[];
    const int tid = threadIdx.x;

    if (blockIdx.x >= 128) {
        const int e = blockIdx.x - 128;
        float* cws  = sm;
        float* clws = cws + 3200;
        float* gw   = clws + 1600;
        float* rlb  = gw + 3840;
        float* xs   = rlb + 7680;
        for (int idx = tid; idx < 3200; idx += 256) cws[idx] = cw[idx];
        for (int idx = tid; idx < 1600; idx += 256) clws[idx] = clw[idx];
        for (int idx = tid; idx < 3840; idx += 256) gw[idx] = gc1_W[idx];

        for (int t = 0; t < 16; t++) {
            int n0 = (e * 16 + t) * 16;
            int b = n0 >> 9, m0 = n0 & 511;
            __syncthreads();
            for (int idx = tid; idx < 5120; idx += 256) {
                int w = idx >> 8, rem = idx & 255;
                int s = rem >> 4, f = rem & 15;
                xs[s * 320 + w * 16 + f] = X[((b * TT + w) * MM + m0) * FF + rem];
            }
            __syncthreads();
            if (tid < 160) {
                int s = tid / 10, k = tid % 10;
                const float* xrow = xs + s * 320;
                const float* ck = cws + k * 320;
                float r = cb[k];
#pragma unroll
                for (int f = 0; f < 16; f++)
#pragma unroll
                    for (int w = 0; w < 20; w++)
                        r += xrow[w * 16 + f] * ck[f * 20 + w];
                const float* clk = clws + k * 160;
                float r0 = clb[k], r1 = clb[k];
#pragma unroll
                for (int f = 0; f < 16; f++)
#pragma unroll
                    for (int j = 0; j < 10; j++) {
                        float wv = clk[f * 10 + j];
                        r0 += xrow[(2 * j) * 16 + f]     * wv;
                        r1 += xrow[(2 * j + 1) * 16 + f] * wv;
                    }
                int o = (t * 16 + s) * 30 + k * 3;
                rlb[o]     = fmaxf(r, 0.f);
                rlb[o + 1] = fmaxf(r0, 0.f);
                rlb[o + 2] = fmaxf(r1, 0.f);
            }
        }
        __syncthreads();
        int h = tid & 127, sg = tid >> 7;
        for (int q = 0; q < 8; q++) {
            const float* rls = rlb + q * 32 * 30;
            int n0z = e * 256 + q * 32;
            float acc[16];
#pragma unroll
            for (int s = 0; s < 16; s++) acc[s] = 0.f;
            for (int qq = 0; qq < 30; qq++) {
                float wv = gw[qq * 128 + h];
#pragma unroll
                for (int s = 0; s < 16; s++)
                    acc[s] += rls[(sg * 16 + s) * 30 + qq] * wv;
            }
#pragma unroll
            for (int s = 0; s < 16; s++)
                g_Z[(n0z + sg * 16 + s) * HH + h] = acc[s];
        }
        return;
    }

    // ================= GRU branch =================
    float* whh4 = sm;
    float* hbuf = sm + 49152;
    float* xbuf = hbuf + 128 * HS;

    const int lane = tid & 31;
    const int warp = tid >> 5;
    const int n0 = blockIdx.x * 32;
    const int b = n0 >> 9, m0 = n0 & 511;
    const int sb = warp * 4;
    const float* Xw = X + ((size_t)b * TT * MM + m0 + sb) * FF;
    float* xw = xbuf + warp * 64;

    for (int idx = tid * 4; idx < G3 * HH; idx += 256 * 4)
        *(float4*)&whh4[idx] = *(const float4*)&g_whh4[idx];
    for (int idx = tid; idx < 128 * HS; idx += 256) hbuf[idx] = 0.f;

    ull br[2], bz[2], bnx[2], bnh[2];
#pragma unroll
    for (int p = 0; p < 2; p++) {
        int gg = 64 * p + 2 * lane;
        float2 t1 = *(const float2*)(bih + gg);
        float2 t2 = *(const float2*)(bhh + gg);
        br[p] = add2(*(const ull*)&t1, *(const ull*)&t2);
        t1 = *(const float2*)(bih + 128 + gg);
        t2 = *(const float2*)(bhh + 128 + gg);
        bz[p] = add2(*(const ull*)&t1, *(const ull*)&t2);
        t1 = *(const float2*)(bih + 256 + gg);
        bnx[p] = *(const ull*)&t1;
        t2 = *(const float2*)(bhh + 256 + gg);
        bnh[p] = *(const ull*)&t2;
    }
    __syncthreads();

    float2 xr = *(const float2*)(Xw + 2 * lane);

    for (int t = 0; t < TT; t++) {
        *(float2*)(xw + 2 * lane) = xr;
        __syncwarp();
        if (t + 1 < TT)
            xr = *(const float2*)(Xw + (t + 1) * MM * FF + 2 * lane);

        ull ar[4][2], az[4][2], axn[4][2], ahn[4][2];
#pragma unroll
        for (int s = 0; s < 4; s++)
#pragma unroll
            for (int p = 0; p < 2; p++) {
                ar[s][p] = br[p]; az[s][p] = bz[p];
                axn[s][p] = bnx[p]; ahn[s][p] = bnh[p];
            }

#pragma unroll 4
        for (int f = 0; f < FF; f++) {
            const float* wf = g_wih4 + f * G3 + lane * 4;
            ulonglong2 w01 = *(const ulonglong2*)(wf);
            ulonglong2 w23 = *(const ulonglong2*)(wf + 128);
            ulonglong2 w45 = *(const ulonglong2*)(wf + 256);
#pragma unroll
            for (int s = 0; s < 4; s++) {
                ull xd = fdup(xw[s * 16 + f]);
                fma2(ar[s][0], xd, w01.x);  fma2(ar[s][1], xd, w01.y);
                fma2(az[s][0], xd, w23.x);  fma2(az[s][1], xd, w23.y);
                fma2(axn[s][0], xd, w45.x); fma2(axn[s][1], xd, w45.y);
            }
        }
#pragma unroll 2
        for (int k = 0; k < HH; k++) {
            const float* wk = whh4 + k * G3 + lane * 4;
            ulonglong2 w01 = *(const ulonglong2*)(wk);
            ulonglong2 w23 = *(const ulonglong2*)(wk + 128);
            ulonglong2 w45 = *(const ulonglong2*)(wk + 256);
            float4 h4 = *(const float4*)(hbuf + k * HS + sb);
            ull hd0 = fdup(h4.x), hd1 = fdup(h4.y);
            ull hd2 = fdup(h4.z), hd3 = fdup(h4.w);
            fma2(ar[0][0], hd0, w01.x);  fma2(ar[0][1], hd0, w01.y);
            fma2(az[0][0], hd0, w23.x);  fma2(az[0][1], hd0, w23.y);
            fma2(ahn[0][0], hd0, w45.x); fma2(ahn[0][1], hd0, w45.y);
            fma2(ar[1][0], hd1, w01.x);  fma2(ar[1][1], hd1, w01.y);
            fma2(az[1][0], hd1, w23.x);  fma2(az[1][1], hd1, w23.y);
            fma2(ahn[1][0], hd1, w45.x); fma2(ahn[1][1], hd1, w45.y);
            fma2(ar[2][0], hd2, w01.x);  fma2(ar[2][1], hd2, w01.y);
            fma2(az[2][0], hd2, w23.x);  fma2(az[2][1], hd2, w23.y);
            fma2(ahn[2][0], hd2, w45.x); fma2(ahn[2][1], hd2, w45.y);
            fma2(ar[3][0], hd3, w01.x);  fma2(ar[3][1], hd3, w01.y);
            fma2(az[3][0], hd3, w23.x);  fma2(az[3][1], hd3, w23.y);
            fma2(ahn[3][0], hd3, w45.x); fma2(ahn[3][1], hd3, w45.y);
        }
        __syncwarp();
#pragma unroll
        for (int s = 0; s < 4; s++) {
            int col = sb + s;
#pragma unroll
            for (int p = 0; p < 2; p++) {
                int h0 = 64 * p + 2 * lane;
                float2 rv = fup(ar[s][p]);
                float2 zv = fup(az[s][p]);
                float2 xv = fup(axn[s][p]);
                float2 hv = fup(ahn[s][p]);
                float hold0 = hbuf[h0 * HS + col];
                float hold1 = hbuf[(h0 + 1) * HS + col];
                float r0 = fsig_a(rv.x), z0 = fsig_a(zv.x);
                float nn0 = ftanh_a(xv.x + r0 * hv.x);
                float r1 = fsig_a(rv.y), z1 = fsig_a(zv.y);
                float nn1 = ftanh_a(xv.y + r1 * hv.y);
                hbuf[h0 * HS + col]       = nn0 + z0 * (hold0 - nn0);
                hbuf[(h0 + 1) * HS + col] = nn1 + z1 * (hold1 - nn1);
            }
        }
        __syncwarp();
    }

#pragma unroll
    for (int q = 0; q < 4; q++) {
        int h = 32 * q + lane;
#pragma unroll
        for (int s = 0; s < 4; s++)
            g_hid[(n0 + sb + s) * HH + h] = hbuf[h * HS + sb + s];
    }

    // ---- fused p1/p2 + exp epilogue (pre-transposed weights, coalesced) ----
    float* w1t = whh4;            // [h][66]
    float* w2t = whh4 + 128 * 66;
    __syncthreads();
    for (int idx = tid; idx < HH * HALF; idx += 256) {
        int h = idx >> 6, kk = idx & 63;
        w1t[h * 66 + kk] = g_w1t[idx];
        w2t[h * 66 + kk] = g_w2t[idx];
    }
    __syncthreads();

    float2 b1v = *(const float2*)(b1 + 2 * lane);
    ull p1a[4], p2a[4];
#pragma unroll
    for (int s = 0; s < 4; s++) { p1a[s] = *(const ull*)&b1v; p2a[s] = 0ULL; }
#pragma unroll 2
    for (int h = 0; h < HH; h++) {
        ull w1 = *(const ull*)&w1t[h * 66 + 2 * lane];
        ull w2 = *(const ull*)&w2t[h * 66 + 2 * lane];
        float4 h4 = *(const float4*)(hbuf + h * HS + sb);
        ull hd0 = fdup(h4.x), hd1 = fdup(h4.y);
        ull hd2 = fdup(h4.z), hd3 = fdup(h4.w);
        fma2(p1a[0], hd0, w1); fma2(p2a[0], hd0, w2);
        fma2(p1a[1], hd1, w1); fma2(p2a[1], hd1, w2);
        fma2(p1a[2], hd2, w1); fma2(p2a[2], hd2, w2);
        fma2(p1a[3], hd3, w1); fma2(p2a[3], hd3, w2);
    }
#pragma unroll
    for (int s = 0; s < 4; s++) {
        int n = n0 + sb + s;
        float2 p1v = fup(p1a[s]);
        float2 p2v = fup(p2a[s]);
        *(float2*)&g_p1[n * 64 + 2 * lane] = p1v;
        *(float2*)&g_p2[n * 64 + 2 * lane] = p2v;
        float2 e1v = { __expf(fminf(p1v.x, 60.f)), __expf(fminf(p1v.y, 60.f)) };
        float2 e2v = { __expf(fminf(p2v.x, 60.f)), __expf(fminf(p2v.y, 60.f)) };
        *(float2*)&g_e1[n * 64 + 2 * lane] = e1v;
        *(float2*)&g_e2[n * 64 + 2 * lane] = e2v;
    }
}

// ============================================================================
// Kernel 3: amx, persistent (444 CTAs loop over 512 tiles)
// ============================================================================
__global__ void __launch_bounds__(256) amx_kernel(
    const float* __restrict__ V, const float* __restrict__ bv)
{
    extern __shared__ float sma[];
    float* p1s = sma;
    float* e1s = p1s + 64 * 66;
    float* p2s = e1s + 64 * 66;
    float* e2s = p2s + 64 * 66;
    float* Vs  = e2s + 64 * 66;
    int tid = threadIdx.x;
    if (tid < 64) Vs[tid] = V[tid];
    float cst = bv[0] - g_sumV;
    int tyy = tid >> 4, txx = tid & 15;

    for (int tile = blockIdx.x; tile < 512; tile += gridDim.x) {
        int b = tile >> 6;
        int i0 = ((tile >> 3) & 7) * 64;
        int j0 = (tile & 7) * 64;
        __syncthreads();
        for (int idx = tid; idx < 64 * 64; idx += 256) {
            int r = idx >> 6, k = idx & 63;
            p1s[r * 66 + k] = g_p1[(b * MM + j0 + r) * HALF + k];
            e1s[r * 66 + k] = g_e1[(b * MM + j0 + r) * HALF + k];
            p2s[r * 66 + k] = g_p2[(b * MM + i0 + r) * HALF + k];
            e2s[r * 66 + k] = g_e2[(b * MM + i0 + r) * HALF + k];
        }
        __syncthreads();
        float accp[4][4], acce[4][4];
#pragma unroll
        for (int r = 0; r < 4; r++)
#pragma unroll
            for (int c = 0; c < 4; c++) { accp[r][c] = 0.f; acce[r][c] = 0.f; }

#pragma unroll 2
        for (int kp = 0; kp < 32; kp++) {
            int k = 2 * kp;
            float vk0 = Vs[k], vk1 = Vs[k + 1];
            ull p2r[4], e2r[4], p1c[4], e1c[4];
#pragma unroll
            for (int r = 0; r < 4; r++) {
                p2r[r] = *(const ull*)&p2s[(tyy + 16 * r) * 66 + k];
                e2r[r] = *(const ull*)&e2s[(tyy + 16 * r) * 66 + k];
            }
#pragma unroll
            for (int c = 0; c < 4; c++) {
                p1c[c] = *(const ull*)&p1s[(txx + 16 * c) * 66 + k];
                e1c[c] = *(const ull*)&e1s[(txx + 16 * c) * 66 + k];
            }
#pragma unroll
            for (int r = 0; r < 4; r++)
#pragma unroll
                for (int c = 0; c < 4; c++) {
                    float2 v = fup(add2(p1c[c], p2r[r]));
                    float2 m = fup(mul2(e1c[c], e2r[r]));
                    accp[r][c] = fmaf(fmaxf(v.x, 0.f), vk0, accp[r][c]);
                    accp[r][c] = fmaf(fmaxf(v.y, 0.f), vk1, accp[r][c]);
                    acce[r][c] = fmaf(fminf(m.x, 1.f), vk0, acce[r][c]);
                    acce[r][c] = fmaf(fminf(m.y, 1.f), vk1, acce[r][c]);
                }
        }
        float ps[4] = {0.f, 0.f, 0.f, 0.f};
#pragma unroll
        for (int r = 0; r < 4; r++) {
            int i = i0 + tyy + 16 * r;
#pragma unroll
            for (int c = 0; c < 4; c++) {
                int j = j0 + txx + 16 * c;
                float val = accp[r][c] + acce[r][c] + cst;
                g_amx[(b * MM + i) * MM + j] = val;
                ps[c] += val * val;
            }
        }
        __syncthreads();
        float* scr = p1s;
#pragma unroll
        for (int c = 0; c < 4; c++)
            scr[(txx + 16 * c) * 16 + tyy] = ps[c];
        __syncthreads();
        if (tid < 64) {
            float s = 0.f;
#pragma unroll
            for (int q = 0; q < 16; q++) s += scr[tid * 16 + q];
            g_cs[(b * 8 + ((tile >> 3) & 7)) * MM + j0 + tid] = s;
        }
    }
}

// Kernel 3b
__global__ void rnrm_kernel()
{
    int idx = blockIdx.x * 512 + threadIdx.x;
    int b = idx >> 9, j = idx & 511;
    float s = 0.f;
#pragma unroll
    for (int t = 0; t < 8; t++) s += g_cs[(b * 8 + t) * MM + j];
    g_rnrm[idx] = 1.f / fmaxf(sqrtf(s), 1e-12f);
}

// ============================================================================
// Kernel 5: gateA 128x128 tile, 256 thr, double-buffered (reg prefetch).
// ============================================================================
__global__ void __launch_bounds__(256) gateA_kernel(
    const float* __restrict__ Wb, const float* __restrict__ adj,
    const float* __restrict__ wb)
{
    __shared__ float As[16 * 132];
    __shared__ float Bs[16 * 128];
    int b = blockIdx.z, i0 = blockIdx.y * 128, j0 = blockIdx.x * 128;
    const float* Ab = g_amx + b * MM * MM;
    const float* rn = g_rnrm + b * MM;
    int tid = threadIdx.x;
    int ty = tid >> 4, tx = tid & 15;
    int lrow = tid >> 1, lkq = (tid & 1) * 8;
    ull acc[4][8];
#pragma unroll
    for (int r = 0; r < 4; r++)
#pragma unroll
        for (int c = 0; c < 8; c++) acc[r][c] = 0ULL;

    float4 avp[2], rvp[2], bvp[2];
#pragma unroll
    for (int half = 0; half < 2; half++) {
        int kq = lkq + half * 4;
        avp[half] = *(const float4*)(Ab + (i0 + lrow) * MM + kq);
        rvp[half] = *(const float4*)(rn + kq);
    }
#pragma unroll
    for (int q = 0; q < 2; q++) {
        int idx = (tid + q * 256) * 4;
        int kk = idx >> 7, col = idx & 127;
        bvp[q] = *(const float4*)&Wb[kk * MM + j0 + col];
    }

    for (int kt = 0; kt < MM; kt += 16) {
#pragma unroll
        for (int half = 0; half < 2; half++) {
            int kq = lkq + half * 4;
            As[(kq + 0) * 132 + lrow] = avp[half].x * rvp[half].x;
            As[(kq + 1) * 132 + lrow] = avp[half].y * rvp[half].y;
            As[(kq + 2) * 132 + lrow] = avp[half].z * rvp[half].z;
            As[(kq + 3) * 132 + lrow] = avp[half].w * rvp[half].w;
        }
#pragma unroll
        for (int q = 0; q < 2; q++) {
            int idx = (tid + q * 256) * 4;
            int kk = idx >> 7, col = idx & 127;
            *(float4*)&Bs[kk * 128 + col] = bvp[q];
        }
        __syncthreads();
        if (kt + 16 < MM) {
            int ktn = kt + 16;
#pragma unroll
            for (int half = 0; half < 2; half++) {
                int kq = lkq + half * 4;
                avp[half] = *(const float4*)(Ab + (i0 + lrow) * MM + ktn + kq);
                rvp[half] = *(const float4*)(rn + ktn + kq);
            }
#pragma unroll
            for (int q = 0; q < 2; q++) {
                int idx = (tid + q * 256) * 4;
                int kk = idx >> 7, col = idx & 127;
                bvp[q] = *(const float4*)&Wb[(ktn + kk) * MM + j0 + col];
            }
        }
#pragma unroll
        for (int kk = 0; kk < 16; kk++) {
            ull a[4], bb[8];
#pragma unroll
            for (int r = 0; r < 4; r++)
                a[r] = *(const ull*)&As[kk * 132 + 2 * (ty + 16 * r)];
#pragma unroll
            for (int c = 0; c < 8; c++)
                bb[c] = fdup(Bs[kk * 128 + tx + 16 * c]);
#pragma unroll
            for (int r = 0; r < 4; r++)
#pragma unroll
                for (int c = 0; c < 8; c++)
                    fma2(acc[r][c], a[r], bb[c]);
        }
        __syncthreads();
    }
    float wbv = wb[0];
#pragma unroll
    for (int r = 0; r < 4; r++) {
        int ia = i0 + 2 * (ty + 16 * r);
#pragma unroll
        for (int c = 0; c < 8; c++) {
            int j = j0 + tx + 16 * c;
            float2 val = fup(acc[r][c]);
            float rj = rn[j];
            float aj0 = adj[ia * MM + j], aj1 = adj[(ia + 1) * MM + j];
            float ax0 = Ab[ia * MM + j] * rj, ax1 = Ab[(ia + 1) * MM + j] * rj;
            float cg0 = fsig_a(val.x + wbv);
            float cg1 = fsig_a(val.y + wbv);
            g_A[(b * MM + ia) * MM + j]     = aj0 * cg0 + ax0 * (1.f - cg0);
            g_A[(b * MM + ia + 1) * MM + j] = aj1 * cg1 + ax1 * (1.f - cg1);
        }
    }
}

// ============================================================================
// Kernel 7: h1 = relu(A @ Z + gc1_b), 64x64 tiles, grid (2,8,8)
// ============================================================================
__global__ void __launch_bounds__(256) h1_kernel(const float* __restrict__ gc1_b)
{
    __shared__ ull Asd[64 * 17];
    __shared__ float Bs[16 * 64];
    int b = blockIdx.z, i0 = blockIdx.y * 64, j0 = blockIdx.x * 64;
    const float* Ab = g_A + b * MM * MM;
    const float* Zb = g_Z + b * MM * HH;
    int tid = threadIdx.x;
    int ty = tid >> 4, tx = tid & 15;
    int lrow = tid >> 2, lkq = (tid & 3) * 4;
    ull acc[4][2];
#pragma unroll
    for (int r = 0; r < 4; r++) { acc[r][0] = 0ULL; acc[r][1] = 0ULL; }

    for (int kt = 0; kt < MM; kt += 16) {
        float4 av = *(const float4*)(Ab + (i0 + lrow) * MM + kt + lkq);
        Asd[lrow * 17 + lkq]     = fdup(av.x);
        Asd[lrow * 17 + lkq + 1] = fdup(av.y);
        Asd[lrow * 17 + lkq + 2] = fdup(av.z);
        Asd[lrow * 17 + lkq + 3] = fdup(av.w);
#pragma unroll
        for (int q = 0; q < 4; q++) {
            int idx = tid + q * 256;
            int r = idx >> 6, c = idx & 63;
            Bs[r * 64 + c] = Zb[(kt + r) * HH + j0 + c];
        }
        __syncthreads();
#pragma unroll
        for (int kk = 0; kk < 16; kk++) {
            ull b0 = *(const ull*)&Bs[kk * 64 + 2 * tx];
            ull b1 = *(const ull*)&Bs[kk * 64 + 32 + 2 * tx];
#pragma unroll
            for (int r = 0; r < 4; r++) {
                ull a = Asd[(ty + 16 * r) * 17 + kk];
                fma2(acc[r][0], a, b0);
                fma2(acc[r][1], a, b1);
            }
        }
        __syncthreads();
    }
#pragma unroll
    for (int r = 0; r < 4; r++) {
        int i = i0 + ty + 16 * r;
#pragma unroll
        for (int c2 = 0; c2 < 2; c2++) {
            int j = j0 + 2 * tx + 32 * c2;
            float2 val = fup(acc[r][c2]);
            g_h1[(b * MM + i) * HH + j]     = fmaxf(val.x + gc1_b[j], 0.f);
            g_h1[(b * MM + i) * HH + j + 1] = fmaxf(val.y + gc1_b[j + 1], 0.f);
        }
    }
}

// ============================================================================
// Kernel 8: Z2 = h1 @ gc2_W
// ============================================================================
__global__ void __launch_bounds__(320) z2_kernel(const float* __restrict__ gc2_W)
{
    __shared__ float g2[1280];
    __shared__ float h1s[32 * 128];
    int tid = threadIdx.x, n0 = blockIdx.x * 32;
    for (int idx = tid; idx < 1280; idx += 320) g2[idx] = gc2_W[idx];
    for (int idx = tid; idx < 4096; idx += 320) h1s[idx] = g_h1[n0 * HH + idx];
    __syncthreads();
    int s = tid / 10, k = tid % 10;
    float acc = 0.f;
#pragma unroll 8
    for (int j = 0; j < 128; j++)
        acc += h1s[s * 128 + j] * g2[j * 10 + k];
    g_Z2[(n0 + s) * KK + k] = acc;
}

// ============================================================================
// Kernel 9: out_spatial = relu(A @ Z2 + gc2_b)
// ============================================================================
__global__ void __launch_bounds__(320) spatial_kernel(const float* __restrict__ gc2_b)
{
    __shared__ float z2s[MM * KK];
    __shared__ float ats[32 * 33];
    int b = blockIdx.y, i0 = blockIdx.x * 32;
    int tid = threadIdx.x;
    for (int idx = tid; idx < MM * KK; idx += 320) z2s[idx] = g_Z2[b * MM * KK + idx];
    int il = tid / 10, k = tid % 10;
    float acc = 0.f;
    for (int j0 = 0; j0 < MM; j0 += 32) {
        __syncthreads();
        for (int idx = tid; idx < 1024; idx += 320) {
            int r = idx >> 5, c = idx & 31;
            ats[r * 33 + c] = g_A[b * MM * MM + (i0 + r) * MM + j0 + c];
        }
        __syncthreads();
#pragma unroll 8
        for (int c = 0; c < 32; c++)
            acc += ats[il * 33 + c] * z2s[(j0 + c) * KK + k];
    }
    g_sp[(b * MM + i0 + il) * KK + k] = fmaxf(acc + gc2_b[k], 0.f);
}

// ============================================================================
// Kernel 10: readout
// ============================================================================
__global__ void readout_kernel(const float* __restrict__ outW,
                               const float* __restrict__ outb,
                               float* __restrict__ outsig)
{
    __shared__ float ws[138];
    int tid = threadIdx.x;
    if (tid < 138) ws[tid] = outW[tid];
    __syncthreads();
    int n = blockIdx.x * 256 + tid;
    float acc = outb[0];
#pragma unroll
    for (int k = 0; k < 10; k++) acc += g_sp[n * KK + k] * ws[k];
#pragma unroll 4
    for (int h = 0; h < 128; h++) acc += g_hid[n * HH + h] * ws[10 + h];
    g_y[n] = acc;
    outsig[n] = fsig_a(acc);
}

// Kernel 11: loss (exact softplus)
__global__ void loss_kernel(const float* __restrict__ Y, float* __restrict__ out0)
{
    __shared__ float red[256];
    int tid = threadIdx.x;
    float s = 0.f;
    for (int n = tid; n < BM; n += 256) {
        float v = g_y[n];
        s += fmaxf(v, 0.f) + log1pf(__expf(-fabsf(v))) - Y[n] * v;
    }
    red[tid] = s;
    __syncthreads();
    for (int st = 128; st > 0; st >>= 1) {
        if (tid < st) red[tid] += red[tid + st];
        __syncthreads();
    }
    if (tid == 0) out0[0] = red[0] / (float)BM;
}

// ============================================================================
extern "C" void kernel_launch(void* const* d_in, const int* in_sizes, int n_in,
                              void* d_out, int out_size)
{
    const float* X      = (const float*)d_in[0];
    const float* Y      = (const float*)d_in[1];
    const float* adj    = (const float*)d_in[2];
    const float* V      = (const float*)d_in[3];
    const float* bv     = (const float*)d_in[4];
    const float* W1     = (const float*)d_in[5];
    const float* b1     = (const float*)d_in[6];
    const float* W2     = (const float*)d_in[7];
    const float* Wb     = (const float*)d_in[8];
    const float* wb     = (const float*)d_in[9];
    const float* conv_w = (const float*)d_in[10];
    const float* conv_b = (const float*)d_in[11];
    const float* convl_w= (const float*)d_in[12];
    const float* convl_b= (const float*)d_in[13];
    const float* gWih   = (const float*)d_in[14];
    const float* gWhh   = (const float*)d_in[15];
    const float* gbih   = (const float*)d_in[16];
    const float* gbhh   = (const float*)d_in[17];
    const float* gc1_W  = (const float*)d_in[18];
    const float* gc1_b  = (const float*)d_in[19];
    const float* gc2_W  = (const float*)d_in[20];
    const float* gc2_b  = (const float*)d_in[21];
    const float* out_W  = (const float*)d_in[22];
    const float* out_b  = (const float*)d_in[23];
    float* out = (float*)d_out;

    const int gru_smem = (49152 + 128 * HS + 512) * 4;
    const int amx_smem = (4 * 64 * 66 + 64) * 4;
    cudaFuncSetAttribute(gru_conv_kernel, cudaFuncAttributeMaxDynamicSharedMemorySize, gru_smem);
    cudaFuncSetAttribute(amx_kernel, cudaFuncAttributeMaxDynamicSharedMemorySize, amx_smem);

    wperm_kernel<<<280, 256>>>(gWih, gWhh, W1, W2, V);
    gru_conv_kernel<<<128 + NXT, 256, gru_smem>>>(X, gbih, gbhh, b1,
                                                  conv_w, conv_b, convl_w, convl_b, gc1_W);
    amx_kernel<<<444, 256, amx_smem>>>(V, bv);
    rnrm_kernel<<<8, 512>>>();
    gateA_kernel<<<dim3(4, 4, 8), 256>>>(Wb, adj, wb);
    h1_kernel<<<dim3(2, 8, 8), 256>>>(gc1_b);
    z2_kernel<<<128, 320>>>(gc2_W);
    spatial_kernel<<<dim3(16, 8), 320>>>(gc2_b);
    readout_kernel<<<16, 256>>>(out_W, out_b, out + 1);
    loss_kernel<<<1, 256>>>(Y, out);
}

// round 17
// speedup vs baseline: 1.0011x; 1.0011x over previous
#include <cuda_runtime.h>
#include <cuda_bf16.h>

typedef unsigned long long ull;

#define BB 8
#define TT 20
#define MM 512
#define FF 16
#define HH 128
#define G3 384
#define BM 4096
#define HALF 64
#define KK 10

// ---------------- scratch ----------------
__device__ __align__(128) float g_hid[BM * HH];
__device__ __align__(128) float g_p1[BM * HALF];
__device__ __align__(128) float g_p2[BM * HALF];
__device__ __align__(128) float g_e1[BM * HALF];
__device__ __align__(128) float g_e2[BM * HALF];
__device__ __align__(128) float g_amx[BB * MM * MM];
__device__ __align__(128) float g_cs[BB * 8 * MM];
__device__ __align__(128) float g_A[BB * MM * MM];
__device__ __align__(128) float g_Z[BM * HH];
__device__ __align__(128) float g_h1[BM * HH];
__device__ __align__(128) float g_Z2[BM * KK];
__device__ __align__(128) float g_sp[BM * KK];
__device__ __align__(128) float g_y[BM];
__device__ __align__(128) float g_wih4[FF * G3];
__device__ __align__(128) float g_whh4[HH * G3];
__device__ __align__(128) float g_w1t[HH * HALF];
__device__ __align__(128) float g_w2t[HH * HALF];
__device__ float g_sumV;

// ---------------- helpers ----------------
__device__ __forceinline__ float ftanh_a(float x) {
    float r; asm("tanh.approx.f32 %0, %1;" : "=f"(r) : "f"(x)); return r;
}
__device__ __forceinline__ float fsig_a(float x) {
    return fmaf(ftanh_a(0.5f * x), 0.5f, 0.5f);
}
__device__ __forceinline__ ull fdup(float x) {
    ull r; asm("mov.b64 %0, {%1, %1};" : "=l"(r) : "f"(x)); return r;
}
__device__ __forceinline__ float2 fup(ull v) {
    float2 r; asm("mov.b64 {%0, %1}, %2;" : "=f"(r.x), "=f"(r.y) : "l"(v)); return r;
}
__device__ __forceinline__ void fma2(ull& d, ull a, ull b) {
    asm("fma.rn.f32x2 %0, %1, %2, %0;" : "+l"(d) : "l"(a), "l"(b));
}
__device__ __forceinline__ ull add2(ull a, ull b) {
    ull r; asm("add.rn.f32x2 %0, %1, %2;" : "=l"(r) : "l"(a), "l"(b)); return r;
}
__device__ __forceinline__ ull mul2(ull a, ull b) {
    ull r; asm("mul.rn.f32x2 %0, %1, %2;" : "=l"(r) : "l"(a), "l"(b)); return r;
}

// ============================================================================
// Kernel 0: permute Wih, Whh; transpose W1, W2; sumV. 280 blocks x 256.
// ============================================================================
__global__ void wperm_kernel(const float* __restrict__ Wih,
                             const float* __restrict__ Whh,
                             const float* __restrict__ W1,
                             const float* __restrict__ W2,
                             const float* __restrict__ V)
{
    int i = blockIdx.x * 256 + threadIdx.x;
    if (i < G3 * FF) {
        int f = i / G3, rem = i % G3;
        int wq = rem >> 7, r2 = rem & 127;
        int lane = r2 >> 2, e = r2 & 3;
        int g = wq * 128 + ((e >> 1) * 64) + 2 * lane + (e & 1);
        g_wih4[i] = Wih[g * FF + f];
    }
    int j = i - G3 * FF;
    if (j >= 0 && j < G3 * HH) {
        int k = j / G3, rem = j % G3;
        int wq = rem >> 7, r2 = rem & 127;
        int lane = r2 >> 2, e = r2 & 3;
        int g = wq * 128 + ((e >> 1) * 64) + 2 * lane + (e & 1);
        g_whh4[j] = Whh[g * HH + k];
    }
    int j2 = j - G3 * HH;
    if (j2 >= 0 && j2 < HH * HALF) {
        int h = j2 >> 6, kk = j2 & 63;
        g_w1t[j2] = W1[kk * HH + h];
    }
    int j3 = j2 - HH * HALF;
    if (j3 >= 0 && j3 < HH * HALF) {
        int h = j3 >> 6, kk = j3 & 63;
        g_w2t[j3] = W2[kk * HH + h];
    }
    if (i == 0) {
        float s = 0.f;
#pragma unroll
        for (int k = 0; k < HALF; k++) s += V[k];
        g_sumV = s;
    }
}

// ============================================================================
// Kernel 1: combined GRU (blocks 0..127) + conv/zk (blocks 128..143).
// ============================================================================
#define HS 36
#define NXT 16
__global__ void __launch_bounds__(256, 1) gru_conv_kernel(
    const float* __restrict__ X,
    const float* __restrict__ bih, const float* __restrict__ bhh,
    const float* __restrict__ b1,
    const float* __restrict__ cw, const float* __restrict__ cb,
    const float* __restrict__ clw, const float* __restrict__ clb,
    const float* __restrict__ gc1_W)
{
    extern __shared__ float sm[];
    const int tid = threadIdx.x;

    if (blockIdx.x >= 128) {
        const int e = blockIdx.x - 128;
        float* cws  = sm;
        float* clws = cws + 3200;
        float* gw   = clws + 1600;
        float* rlb  = gw + 3840;
        float* xs   = rlb + 7680;
        for (int idx = tid; idx < 3200; idx += 256) cws[idx] = cw[idx];
        for (int idx = tid; idx < 1600; idx += 256) clws[idx] = clw[idx];
        for (int idx = tid; idx < 3840; idx += 256) gw[idx] = gc1_W[idx];

        for (int t = 0; t < 16; t++) {
            int n0 = (e * 16 + t) * 16;
            int b = n0 >> 9, m0 = n0 & 511;
            __syncthreads();
            for (int idx = tid; idx < 5120; idx += 256) {
                int w = idx >> 8, rem = idx & 255;
                int s = rem >> 4, f = rem & 15;
                xs[s * 320 + w * 16 + f] = X[((b * TT + w) * MM + m0) * FF + rem];
            }
            __syncthreads();
            if (tid < 160) {
                int s = tid / 10, k = tid % 10;
                const float* xrow = xs + s * 320;
                const float* ck = cws + k * 320;
                float r = cb[k];
#pragma unroll
                for (int f = 0; f < 16; f++)
#pragma unroll
                    for (int w = 0; w < 20; w++)
                        r += xrow[w * 16 + f] * ck[f * 20 + w];
                const float* clk = clws + k * 160;
                float r0 = clb[k], r1 = clb[k];
#pragma unroll
                for (int f = 0; f < 16; f++)
#pragma unroll
                    for (int j = 0; j < 10; j++) {
                        float wv = clk[f * 10 + j];
                        r0 += xrow[(2 * j) * 16 + f]     * wv;
                        r1 += xrow[(2 * j + 1) * 16 + f] * wv;
                    }
                int o = (t * 16 + s) * 30 + k * 3;
                rlb[o]     = fmaxf(r, 0.f);
                rlb[o + 1] = fmaxf(r0, 0.f);
                rlb[o + 2] = fmaxf(r1, 0.f);
            }
        }
        __syncthreads();
        int h = tid & 127, sg = tid >> 7;
        for (int q = 0; q < 8; q++) {
            const float* rls = rlb + q * 32 * 30;
            int n0z = e * 256 + q * 32;
            float acc[16];
#pragma unroll
            for (int s = 0; s < 16; s++) acc[s] = 0.f;
            for (int qq = 0; qq < 30; qq++) {
                float wv = gw[qq * 128 + h];
#pragma unroll
                for (int s = 0; s < 16; s++)
                    acc[s] += rls[(sg * 16 + s) * 30 + qq] * wv;
            }
#pragma unroll
            for (int s = 0; s < 16; s++)
                g_Z[(n0z + sg * 16 + s) * HH + h] = acc[s];
        }
        return;
    }

    // ================= GRU branch =================
    float* whh4 = sm;
    float* hbuf = sm + 49152;
    float* xbuf = hbuf + 128 * HS;

    const int lane = tid & 31;
    const int warp = tid >> 5;
    const int n0 = blockIdx.x * 32;
    const int b = n0 >> 9, m0 = n0 & 511;
    const int sb = warp * 4;
    const float* Xw = X + ((size_t)b * TT * MM + m0 + sb) * FF;
    float* xw = xbuf + warp * 64;

    for (int idx = tid * 4; idx < G3 * HH; idx += 256 * 4)
        *(float4*)&whh4[idx] = *(const float4*)&g_whh4[idx];
    for (int idx = tid; idx < 128 * HS; idx += 256) hbuf[idx] = 0.f;

    ull br[2], bz[2], bnx[2], bnh[2];
#pragma unroll
    for (int p = 0; p < 2; p++) {
        int gg = 64 * p + 2 * lane;
        float2 t1 = *(const float2*)(bih + gg);
        float2 t2 = *(const float2*)(bhh + gg);
        br[p] = add2(*(const ull*)&t1, *(const ull*)&t2);
        t1 = *(const float2*)(bih + 128 + gg);
        t2 = *(const float2*)(bhh + 128 + gg);
        bz[p] = add2(*(const ull*)&t1, *(const ull*)&t2);
        t1 = *(const float2*)(bih + 256 + gg);
        bnx[p] = *(const ull*)&t1;
        t2 = *(const float2*)(bhh + 256 + gg);
        bnh[p] = *(const ull*)&t2;
    }
    __syncthreads();

    float2 xr = *(const float2*)(Xw + 2 * lane);

    for (int t = 0; t < TT; t++) {
        *(float2*)(xw + 2 * lane) = xr;
        __syncwarp();
        if (t + 1 < TT)
            xr = *(const float2*)(Xw + (t + 1) * MM * FF + 2 * lane);

        ull ar[4][2], az[4][2], axn[4][2], ahn[4][2];
#pragma unroll
        for (int s = 0; s < 4; s++)
#pragma unroll
            for (int p = 0; p < 2; p++) {
                ar[s][p] = br[p]; az[s][p] = bz[p];
                axn[s][p] = bnx[p]; ahn[s][p] = bnh[p];
            }

#pragma unroll 4
        for (int f = 0; f < FF; f++) {
            const float* wf = g_wih4 + f * G3 + lane * 4;
            ulonglong2 w01 = *(const ulonglong2*)(wf);
            ulonglong2 w23 = *(const ulonglong2*)(wf + 128);
            ulonglong2 w45 = *(const ulonglong2*)(wf + 256);
#pragma unroll
            for (int s = 0; s < 4; s++) {
                ull xd = fdup(xw[s * 16 + f]);
                fma2(ar[s][0], xd, w01.x);  fma2(ar[s][1], xd, w01.y);
                fma2(az[s][0], xd, w23.x);  fma2(az[s][1], xd, w23.y);
                fma2(axn[s][0], xd, w45.x); fma2(axn[s][1], xd, w45.y);
            }
        }
#pragma unroll 2
        for (int k = 0; k < HH; k++) {
            const float* wk = whh4 + k * G3 + lane * 4;
            ulonglong2 w01 = *(const ulonglong2*)(wk);
            ulonglong2 w23 = *(const ulonglong2*)(wk + 128);
            ulonglong2 w45 = *(const ulonglong2*)(wk + 256);
            float4 h4 = *(const float4*)(hbuf + k * HS + sb);
            ull hd0 = fdup(h4.x), hd1 = fdup(h4.y);
            ull hd2 = fdup(h4.z), hd3 = fdup(h4.w);
            fma2(ar[0][0], hd0, w01.x);  fma2(ar[0][1], hd0, w01.y);
            fma2(az[0][0], hd0, w23.x);  fma2(az[0][1], hd0, w23.y);
            fma2(ahn[0][0], hd0, w45.x); fma2(ahn[0][1], hd0, w45.y);
            fma2(ar[1][0], hd1, w01.x);  fma2(ar[1][1], hd1, w01.y);
            fma2(az[1][0], hd1, w23.x);  fma2(az[1][1], hd1, w23.y);
            fma2(ahn[1][0], hd1, w45.x); fma2(ahn[1][1], hd1, w45.y);
            fma2(ar[2][0], hd2, w01.x);  fma2(ar[2][1], hd2, w01.y);
            fma2(az[2][0], hd2, w23.x);  fma2(az[2][1], hd2, w23.y);
            fma2(ahn[2][0], hd2, w45.x); fma2(ahn[2][1], hd2, w45.y);
            fma2(ar[3][0], hd3, w01.x);  fma2(ar[3][1], hd3, w01.y);
            fma2(az[3][0], hd3, w23.x);  fma2(az[3][1], hd3, w23.y);
            fma2(ahn[3][0], hd3, w45.x); fma2(ahn[3][1], hd3, w45.y);
        }
        __syncwarp();
#pragma unroll
        for (int s = 0; s < 4; s++) {
            int col = sb + s;
#pragma unroll
            for (int p = 0; p < 2; p++) {
                int h0 = 64 * p + 2 * lane;
                float2 rv = fup(ar[s][p]);
                float2 zv = fup(az[s][p]);
                float2 xv = fup(axn[s][p]);
                float2 hv = fup(ahn[s][p]);
                float hold0 = hbuf[h0 * HS + col];
                float hold1 = hbuf[(h0 + 1) * HS + col];
                float r0 = fsig_a(rv.x), z0 = fsig_a(zv.x);
                float nn0 = ftanh_a(xv.x + r0 * hv.x);
                float r1 = fsig_a(rv.y), z1 = fsig_a(zv.y);
                float nn1 = ftanh_a(xv.y + r1 * hv.y);
                hbuf[h0 * HS + col]       = nn0 + z0 * (hold0 - nn0);
                hbuf[(h0 + 1) * HS + col] = nn1 + z1 * (hold1 - nn1);
            }
        }
        __syncwarp();
    }

#pragma unroll
    for (int q = 0; q < 4; q++) {
        int h = 32 * q + lane;
#pragma unroll
        for (int s = 0; s < 4; s++)
            g_hid[(n0 + sb + s) * HH + h] = hbuf[h * HS + sb + s];
    }

    // ---- fused p1/p2 + exp epilogue ----
    float* w1t = whh4;
    float* w2t = whh4 + 128 * 66;
    __syncthreads();
    for (int idx = tid; idx < HH * HALF; idx += 256) {
        int h = idx >> 6, kk = idx & 63;
        w1t[h * 66 + kk] = g_w1t[idx];
        w2t[h * 66 + kk] = g_w2t[idx];
    }
    __syncthreads();

    float2 b1v = *(const float2*)(b1 + 2 * lane);
    ull p1a[4], p2a[4];
#pragma unroll
    for (int s = 0; s < 4; s++) { p1a[s] = *(const ull*)&b1v; p2a[s] = 0ULL; }
#pragma unroll 2
    for (int h = 0; h < HH; h++) {
        ull w1 = *(const ull*)&w1t[h * 66 + 2 * lane];
        ull w2 = *(const ull*)&w2t[h * 66 + 2 * lane];
        float4 h4 = *(const float4*)(hbuf + h * HS + sb);
        ull hd0 = fdup(h4.x), hd1 = fdup(h4.y);
        ull hd2 = fdup(h4.z), hd3 = fdup(h4.w);
        fma2(p1a[0], hd0, w1); fma2(p2a[0], hd0, w2);
        fma2(p1a[1], hd1, w1); fma2(p2a[1], hd1, w2);
        fma2(p1a[2], hd2, w1); fma2(p2a[2], hd2, w2);
        fma2(p1a[3], hd3, w1); fma2(p2a[3], hd3, w2);
    }
#pragma unroll
    for (int s = 0; s < 4; s++) {
        int n = n0 + sb + s;
        float2 p1v = fup(p1a[s]);
        float2 p2v = fup(p2a[s]);
        *(float2*)&g_p1[n * 64 + 2 * lane] = p1v;
        *(float2*)&g_p2[n * 64 + 2 * lane] = p2v;
        float2 e1v = { __expf(fminf(p1v.x, 60.f)), __expf(fminf(p1v.y, 60.f)) };
        float2 e2v = { __expf(fminf(p2v.x, 60.f)), __expf(fminf(p2v.y, 60.f)) };
        *(float2*)&g_e1[n * 64 + 2 * lane] = e1v;
        *(float2*)&g_e2[n * 64 + 2 * lane] = e2v;
    }
}

// ============================================================================
// Kernel 3: amx, persistent (444 CTAs loop over 512 tiles)
// ============================================================================
__global__ void __launch_bounds__(256) amx_kernel(
    const float* __restrict__ V, const float* __restrict__ bv)
{
    extern __shared__ float sma[];
    float* p1s = sma;
    float* e1s = p1s + 64 * 66;
    float* p2s = e1s + 64 * 66;
    float* e2s = p2s + 64 * 66;
    float* Vs  = e2s + 64 * 66;
    int tid = threadIdx.x;
    if (tid < 64) Vs[tid] = V[tid];
    float cst = bv[0] - g_sumV;
    int tyy = tid >> 4, txx = tid & 15;

    for (int tile = blockIdx.x; tile < 512; tile += gridDim.x) {
        int b = tile >> 6;
        int i0 = ((tile >> 3) & 7) * 64;
        int j0 = (tile & 7) * 64;
        __syncthreads();
        for (int idx = tid; idx < 64 * 64; idx += 256) {
            int r = idx >> 6, k = idx & 63;
            p1s[r * 66 + k] = g_p1[(b * MM + j0 + r) * HALF + k];
            e1s[r * 66 + k] = g_e1[(b * MM + j0 + r) * HALF + k];
            p2s[r * 66 + k] = g_p2[(b * MM + i0 + r) * HALF + k];
            e2s[r * 66 + k] = g_e2[(b * MM + i0 + r) * HALF + k];
        }
        __syncthreads();
        float accp[4][4], acce[4][4];
#pragma unroll
        for (int r = 0; r < 4; r++)
#pragma unroll
            for (int c = 0; c < 4; c++) { accp[r][c] = 0.f; acce[r][c] = 0.f; }

#pragma unroll 2
        for (int kp = 0; kp < 32; kp++) {
            int k = 2 * kp;
            float vk0 = Vs[k], vk1 = Vs[k + 1];
            ull p2r[4], e2r[4], p1c[4], e1c[4];
#pragma unroll
            for (int r = 0; r < 4; r++) {
                p2r[r] = *(const ull*)&p2s[(tyy + 16 * r) * 66 + k];
                e2r[r] = *(const ull*)&e2s[(tyy + 16 * r) * 66 + k];
            }
#pragma unroll
            for (int c = 0; c < 4; c++) {
                p1c[c] = *(const ull*)&p1s[(txx + 16 * c) * 66 + k];
                e1c[c] = *(const ull*)&e1s[(txx + 16 * c) * 66 + k];
            }
#pragma unroll
            for (int r = 0; r < 4; r++)
#pragma unroll
                for (int c = 0; c < 4; c++) {
                    float2 v = fup(add2(p1c[c], p2r[r]));
                    float2 m = fup(mul2(e1c[c], e2r[r]));
                    accp[r][c] = fmaf(fmaxf(v.x, 0.f), vk0, accp[r][c]);
                    accp[r][c] = fmaf(fmaxf(v.y, 0.f), vk1, accp[r][c]);
                    acce[r][c] = fmaf(fminf(m.x, 1.f), vk0, acce[r][c]);
                    acce[r][c] = fmaf(fminf(m.y, 1.f), vk1, acce[r][c]);
                }
        }
        float ps[4] = {0.f, 0.f, 0.f, 0.f};
#pragma unroll
        for (int r = 0; r < 4; r++) {
            int i = i0 + tyy + 16 * r;
#pragma unroll
            for (int c = 0; c < 4; c++) {
                int j = j0 + txx + 16 * c;
                float val = accp[r][c] + acce[r][c] + cst;
                g_amx[(b * MM + i) * MM + j] = val;
                ps[c] += val * val;
            }
        }
        __syncthreads();
        float* scr = p1s;
#pragma unroll
        for (int c = 0; c < 4; c++)
            scr[(txx + 16 * c) * 16 + tyy] = ps[c];
        __syncthreads();
        if (tid < 64) {
            float s = 0.f;
#pragma unroll
            for (int q = 0; q < 16; q++) s += scr[tid * 16 + q];
            g_cs[(b * 8 + ((tile >> 3) & 7)) * MM + j0 + tid] = s;
        }
    }
}

// ============================================================================
// Kernel 5: gateA 128x128 tile, double-buffered, FUSED column-norm prologue.
// ============================================================================
__global__ void __launch_bounds__(256) gateA_kernel(
    const float* __restrict__ Wb, const float* __restrict__ adj,
    const float* __restrict__ wb)
{
    __shared__ float As[16 * 132];
    __shared__ float Bs[16 * 128];
    __shared__ float rn_s[512];
    int b = blockIdx.z, i0 = blockIdx.y * 128, j0 = blockIdx.x * 128;
    const float* Ab = g_amx + b * MM * MM;
    int tid = threadIdx.x;
    int ty = tid >> 4, tx = tid & 15;
    int lrow = tid >> 1, lkq = (tid & 1) * 8;

    // fused rnrm: 512 columns, 8 partials each (L2-hot)
    for (int idx = tid; idx < 512; idx += 256) {
        float s = 0.f;
#pragma unroll
        for (int t = 0; t < 8; t++) s += g_cs[(b * 8 + t) * MM + idx];
        rn_s[idx] = 1.f / fmaxf(sqrtf(s), 1e-12f);
    }

    ull acc[4][8];
#pragma unroll
    for (int r = 0; r < 4; r++)
#pragma unroll
        for (int c = 0; c < 8; c++) acc[r][c] = 0ULL;

    // register prefetch (A and B raw; rn applied at store from smem)
    float4 avp[2], bvp[2];
#pragma unroll
    for (int half = 0; half < 2; half++)
        avp[half] = *(const float4*)(Ab + (i0 + lrow) * MM + lkq + half * 4);
#pragma unroll
    for (int q = 0; q < 2; q++) {
        int idx = (tid + q * 256) * 4;
        int kk = idx >> 7, col = idx & 127;
        bvp[q] = *(const float4*)&Wb[kk * MM + j0 + col];
    }
    __syncthreads();   // rn_s ready

    for (int kt = 0; kt < MM; kt += 16) {
#pragma unroll
        for (int half = 0; half < 2; half++) {
            int kq = lkq + half * 4;
            float4 rv = *(const float4*)(rn_s + kt + kq);
            As[(kq + 0) * 132 + lrow] = avp[half].x * rv.x;
            As[(kq + 1) * 132 + lrow] = avp[half].y * rv.y;
            As[(kq + 2) * 132 + lrow] = avp[half].z * rv.z;
            As[(kq + 3) * 132 + lrow] = avp[half].w * rv.w;
        }
#pragma unroll
        for (int q = 0; q < 2; q++) {
            int idx = (tid + q * 256) * 4;
            int kk = idx >> 7, col = idx & 127;
            *(float4*)&Bs[kk * 128 + col] = bvp[q];
        }
        __syncthreads();
        if (kt + 16 < MM) {
            int ktn = kt + 16;
#pragma unroll
            for (int half = 0; half < 2; half++)
                avp[half] = *(const float4*)(Ab + (i0 + lrow) * MM + ktn + lkq + half * 4);
#pragma unroll
            for (int q = 0; q < 2; q++) {
                int idx = (tid + q * 256) * 4;
                int kk = idx >> 7, col = idx & 127;
                bvp[q] = *(const float4*)&Wb[(ktn + kk) * MM + j0 + col];
            }
        }
#pragma unroll
        for (int kk = 0; kk < 16; kk++) {
            ull a[4], bb[8];
#pragma unroll
            for (int r = 0; r < 4; r++)
                a[r] = *(const ull*)&As[kk * 132 + 2 * (ty + 16 * r)];
#pragma unroll
            for (int c = 0; c < 8; c++)
                bb[c] = fdup(Bs[kk * 128 + tx + 16 * c]);
#pragma unroll
            for (int r = 0; r < 4; r++)
#pragma unroll
                for (int c = 0; c < 8; c++)
                    fma2(acc[r][c], a[r], bb[c]);
        }
        __syncthreads();
    }
    float wbv = wb[0];
#pragma unroll
    for (int r = 0; r < 4; r++) {
        int ia = i0 + 2 * (ty + 16 * r);
#pragma unroll
        for (int c = 0; c < 8; c++) {
            int j = j0 + tx + 16 * c;
            float2 val = fup(acc[r][c]);
            float rj = rn_s[j];
            float aj0 = adj[ia * MM + j], aj1 = adj[(ia + 1) * MM + j];
            float ax0 = Ab[ia * MM + j] * rj, ax1 = Ab[(ia + 1) * MM + j] * rj;
            float cg0 = fsig_a(val.x + wbv);
            float cg1 = fsig_a(val.y + wbv);
            g_A[(b * MM + ia) * MM + j]     = aj0 * cg0 + ax0 * (1.f - cg0);
            g_A[(b * MM + ia + 1) * MM + j] = aj1 * cg1 + ax1 * (1.f - cg1);
        }
    }
}

// ============================================================================
// Kernel 7: h1 = relu(A @ Z + gc1_b), 64x64 tiles, grid (2,8,8)
// ============================================================================
__global__ void __launch_bounds__(256) h1_kernel(const float* __restrict__ gc1_b)
{
    __shared__ ull Asd[64 * 17];
    __shared__ float Bs[16 * 64];
    int b = blockIdx.z, i0 = blockIdx.y * 64, j0 = blockIdx.x * 64;
    const float* Ab = g_A + b * MM * MM;
    const float* Zb = g_Z + b * MM * HH;
    int tid = threadIdx.x;
    int ty = tid >> 4, tx = tid & 15;
    int lrow = tid >> 2, lkq = (tid & 3) * 4;
    ull acc[4][2];
#pragma unroll
    for (int r = 0; r < 4; r++) { acc[r][0] = 0ULL; acc[r][1] = 0ULL; }

    for (int kt = 0; kt < MM; kt += 16) {
        float4 av = *(const float4*)(Ab + (i0 + lrow) * MM + kt + lkq);
        Asd[lrow * 17 + lkq]     = fdup(av.x);
        Asd[lrow * 17 + lkq + 1] = fdup(av.y);
        Asd[lrow * 17 + lkq + 2] = fdup(av.z);
        Asd[lrow * 17 + lkq + 3] = fdup(av.w);
#pragma unroll
        for (int q = 0; q < 4; q++) {
            int idx = tid + q * 256;
            int r = idx >> 6, c = idx & 63;
            Bs[r * 64 + c] = Zb[(kt + r) * HH + j0 + c];
        }
        __syncthreads();
#pragma unroll
        for (int kk = 0; kk < 16; kk++) {
            ull b0 = *(const ull*)&Bs[kk * 64 + 2 * tx];
            ull b1 = *(const ull*)&Bs[kk * 64 + 32 + 2 * tx];
#pragma unroll
            for (int r = 0; r < 4; r++) {
                ull a = Asd[(ty + 16 * r) * 17 + kk];
                fma2(acc[r][0], a, b0);
                fma2(acc[r][1], a, b1);
            }
        }
        __syncthreads();
    }
#pragma unroll
    for (int r = 0; r < 4; r++) {
        int i = i0 + ty + 16 * r;
#pragma unroll
        for (int c2 = 0; c2 < 2; c2++) {
            int j = j0 + 2 * tx + 32 * c2;
            float2 val = fup(acc[r][c2]);
            g_h1[(b * MM + i) * HH + j]     = fmaxf(val.x + gc1_b[j], 0.f);
            g_h1[(b * MM + i) * HH + j + 1] = fmaxf(val.y + gc1_b[j + 1], 0.f);
        }
    }
}

// ============================================================================
// Kernel 8: Z2 = h1 @ gc2_W
// ============================================================================
__global__ void __launch_bounds__(320) z2_kernel(const float* __restrict__ gc2_W)
{
    __shared__ float g2[1280];
    __shared__ float h1s[32 * 128];
    int tid = threadIdx.x, n0 = blockIdx.x * 32;
    for (int idx = tid; idx < 1280; idx += 320) g2[idx] = gc2_W[idx];
    for (int idx = tid; idx < 4096; idx += 320) h1s[idx] = g_h1[n0 * HH + idx];
    __syncthreads();
    int s = tid / 10, k = tid % 10;
    float acc = 0.f;
#pragma unroll 8
    for (int j = 0; j < 128; j++)
        acc += h1s[s * 128 + j] * g2[j * 10 + k];
    g_Z2[(n0 + s) * KK + k] = acc;
}

// ============================================================================
// Kernel 9: out_spatial = relu(A @ Z2 + gc2_b)
// ============================================================================
__global__ void __launch_bounds__(320) spatial_kernel(const float* __restrict__ gc2_b)
{
    __shared__ float z2s[MM * KK];
    __shared__ float ats[32 * 33];
    int b = blockIdx.y, i0 = blockIdx.x * 32;
    int tid = threadIdx.x;
    for (int idx = tid; idx < MM * KK; idx += 320) z2s[idx] = g_Z2[b * MM * KK + idx];
    int il = tid / 10, k = tid % 10;
    float acc = 0.f;
    for (int j0 = 0; j0 < MM; j0 += 32) {
        __syncthreads();
        for (int idx = tid; idx < 1024; idx += 320) {
            int r = idx >> 5, c = idx & 31;
            ats[r * 33 + c] = g_A[b * MM * MM + (i0 + r) * MM + j0 + c];
        }
        __syncthreads();
#pragma unroll 8
        for (int c = 0; c < 32; c++)
            acc += ats[il * 33 + c] * z2s[(j0 + c) * KK + k];
    }
    g_sp[(b * MM + i0 + il) * KK + k] = fmaxf(acc + gc2_b[k], 0.f);
}

// ============================================================================
// Kernel 10: readout
// ============================================================================
__global__ void readout_kernel(const float* __restrict__ outW,
                               const float* __restrict__ outb,
                               float* __restrict__ outsig)
{
    __shared__ float ws[138];
    int tid = threadIdx.x;
    if (tid < 138) ws[tid] = outW[tid];
    __syncthreads();
    int n = blockIdx.x * 256 + tid;
    float acc = outb[0];
#pragma unroll
    for (int k = 0; k < 10; k++) acc += g_sp[n * KK + k] * ws[k];
#pragma unroll 4
    for (int h = 0; h < 128; h++) acc += g_hid[n * HH + h] * ws[10 + h];
    g_y[n] = acc;
    outsig[n] = fsig_a(acc);
}

// Kernel 11: loss (exact softplus)
__global__ void loss_kernel(const float* __restrict__ Y, float* __restrict__ out0)
{
    __shared__ float red[256];
    int tid = threadIdx.x;
    float s = 0.f;
    for (int n = tid; n < BM; n += 256) {
        float v = g_y[n];
        s += fmaxf(v, 0.f) + log1pf(__expf(-fabsf(v))) - Y[n] * v;
    }
    red[tid] = s;
    __syncthreads();
    for (int st = 128; st > 0; st >>= 1) {
        if (tid < st) red[tid] += red[tid + st];
        __syncthreads();
    }
    if (tid == 0) out0[0] = red[0] / (float)BM;
}

// ============================================================================
extern "C" void kernel_launch(void* const* d_in, const int* in_sizes, int n_in,
                              void* d_out, int out_size)
{
    const float* X      = (const float*)d_in[0];
    const float* Y      = (const float*)d_in[1];
    const float* adj    = (const float*)d_in[2];
    const float* V      = (const float*)d_in[3];
    const float* bv     = (const float*)d_in[4];
    const float* W1     = (const float*)d_in[5];
    const float* b1     = (const float*)d_in[6];
    const float* W2     = (const float*)d_in[7];
    const float* Wb     = (const float*)d_in[8];
    const float* wb     = (const float*)d_in[9];
    const float* conv_w = (const float*)d_in[10];
    const float* conv_b = (const float*)d_in[11];
    const float* convl_w= (const float*)d_in[12];
    const float* convl_b= (const float*)d_in[13];
    const float* gWih   = (const float*)d_in[14];
    const float* gWhh   = (const float*)d_in[15];
    const float* gbih   = (const float*)d_in[16];
    const float* gbhh   = (const float*)d_in[17];
    const float* gc1_W  = (const float*)d_in[18];
    const float* gc1_b  = (const float*)d_in[19];
    const float* gc2_W  = (const float*)d_in[20];
    const float* gc2_b  = (const float*)d_in[21];
    const float* out_W  = (const float*)d_in[22];
    const float* out_b  = (const float*)d_in[23];
    float* out = (float*)d_out;

    const int gru_smem = (49152 + 128 * HS + 512) * 4;
    const int amx_smem = (4 * 64 * 66 + 64) * 4;
    cudaFuncSetAttribute(gru_conv_kernel, cudaFuncAttributeMaxDynamicSharedMemorySize, gru_smem);
    cudaFuncSetAttribute(amx_kernel, cudaFuncAttributeMaxDynamicSharedMemorySize, amx_smem);

    wperm_kernel<<<280, 256>>>(gWih, gWhh, W1, W2, V);
    gru_conv_kernel<<<128 + NXT, 256, gru_smem>>>(X, gbih, gbhh, b1,
                                                  conv_w, conv_b, convl_w, convl_b, gc1_W);
    amx_kernel<<<444, 256, amx_smem>>>(V, bv);
    gateA_kernel<<<dim3(4, 4, 8), 256>>>(Wb, adj, wb);
    h1_kernel<<<dim3(2, 8, 8), 256>>>(gc1_b);
    z2_kernel<<<128, 320>>>(gc2_W);
    spatial_kernel<<<dim3(16, 8), 320>>>(gc2_b);
    readout_kernel<<<16, 256>>>(out_W, out_b, out + 1);
    loss_kernel<<<1, 256>>>(Y, out);
}